// round 4
// baseline (speedup 1.0000x reference)
#include <cuda_runtime.h>

// IntraAgg: per batch row b:
//   center  = features[nodes[b]]               (128 f32)
//   neigh_k = features[neighs[b,k]], k=0..31
//   rank by cosine sim (== dot * rsqrt(|n|^2), c-norm drops out of ranking)
//   out[b]  = relu(mean of top-num_sample neighbor rows)
//
// One warp per row. D=128 -> lane holds float4 chunk. All feature-row
// accesses are coalesced 512B warp loads. Table (51MB) is L2-resident.

#define FULLM 0xffffffffu
#define K_NEIGH 32

__global__ __launch_bounds__(256, 8)
void intra_agg_kernel(const float* __restrict__ features,
                      const int*   __restrict__ nodes,
                      const int*   __restrict__ neighs,
                      const int*   __restrict__ nsp,   // may be null
                      float*       __restrict__ out,
                      int B)
{
    const int warp = (blockIdx.x * blockDim.x + threadIdx.x) >> 5;
    const int lane = threadIdx.x & 31;
    if (warp >= B) return;
    const int b = warp;

    int ns = (nsp != nullptr) ? __ldg(nsp) : 10;
    ns = min(max(ns, 1), K_NEIGH);

    const float4* __restrict__ f4 = reinterpret_cast<const float4*>(features);
    const int*    __restrict__ nrow = neighs + (long long)b * K_NEIGH;

    const int node = __ldg(&nodes[b]);
    const float4 c4 = __ldg(&f4[(long long)node * 32 + lane]);

    // ---------------- Phase 1: per-neighbor ranking score on lane k --------
    float score = 0.0f;
    #pragma unroll
    for (int k0 = 0; k0 < K_NEIGH; k0 += 8) {
        int   r[8];
        float4 v[8];
        #pragma unroll
        for (int j = 0; j < 8; ++j) {
            r[j] = __ldg(&nrow[k0 + j]);              // uniform, L1-hot
            v[j] = __ldg(&f4[(long long)r[j] * 32 + lane]);
        }
        #pragma unroll
        for (int j = 0; j < 8; ++j) {
            float pd = c4.x * v[j].x + c4.y * v[j].y + c4.z * v[j].z + c4.w * v[j].w;
            float pn = v[j].x * v[j].x + v[j].y * v[j].y + v[j].z * v[j].z + v[j].w * v[j].w;
            #pragma unroll
            for (int o = 16; o; o >>= 1) {
                pd += __shfl_xor_sync(FULLM, pd, o);
                pn += __shfl_xor_sync(FULLM, pn, o);
            }
            if (lane == k0 + j) score = pd * rsqrtf(pn);
        }
    }

    // ---------------- Phase 2: top-ns selection (set only) -----------------
    // Monotonic float->uint key; excluded lanes use 0 (below any finite key).
    unsigned u = __float_as_uint(score);
    u = (u & 0x80000000u) ? ~u : (u | 0x80000000u);

    unsigned sel = 0u;
    for (int i = 0; i < ns; ++i) {
        unsigned v = ((sel >> lane) & 1u) ? 0u : u;
        unsigned m = __reduce_max_sync(FULLM, v);
        unsigned bal = __ballot_sync(FULLM, v == m);
        sel |= 1u << (__ffs(bal) - 1);                // lowest index on ties
    }

    // ---------------- Phase 3: mean of selected rows + relu ----------------
    float ax = 0.f, ay = 0.f, az = 0.f, aw = 0.f;
    unsigned rem = sel;
    #pragma unroll 5
    for (int i = 0; i < ns; ++i) {
        const int k = __ffs(rem) - 1;
        rem &= rem - 1;
        const int rI = __ldg(&nrow[k]);               // uniform, L1-hot
        const float4 v = __ldg(&f4[(long long)rI * 32 + lane]);
        ax += v.x; ay += v.y; az += v.z; aw += v.w;
    }
    const float inv = 1.0f / (float)ns;
    float4 o;
    o.x = fmaxf(ax * inv, 0.0f);
    o.y = fmaxf(ay * inv, 0.0f);
    o.z = fmaxf(az * inv, 0.0f);
    o.w = fmaxf(aw * inv, 0.0f);
    reinterpret_cast<float4*>(out)[(long long)b * 32 + lane] = o;
}

extern "C" void kernel_launch(void* const* d_in, const int* in_sizes, int n_in,
                              void* d_out, int out_size)
{
    const float* features = (const float*)d_in[0];
    const int*   nodes    = (const int*)d_in[1];
    const int*   neighs   = (const int*)d_in[2];
    const int*   nsp      = (n_in > 3) ? (const int*)d_in[3] : nullptr;

    const int B = in_sizes[1];                 // nodes element count = batch
    const int threads = 256;                   // 8 warps = 8 rows per block
    const int rows_per_block = threads / 32;
    const int grid = (B + rows_per_block - 1) / rows_per_block;

    intra_agg_kernel<<<grid, threads>>>(features, nodes, neighs, nsp,
                                        (float*)d_out, B);
}

// round 5
// speedup vs baseline: 1.4178x; 1.4178x over previous
#include <cuda_runtime.h>

// IntraAgg: per batch row b:
//   center  = features[nodes[b]]               (128 f32)
//   neigh_k = features[neighs[b,k]], k=0..31
//   rank by cosine sim (== dot * rsqrt(|n|^2), c-norm drops out of ranking)
//   out[b]  = relu(mean of top-num_sample neighbor rows)
//
// One warp per row, lane holds a float4 chunk (coalesced 512B row loads,
// table is L2-resident). R5: per-neighbor butterfly reductions replaced by a
// 32-slot transpose-reduction (31 shfl per 16-neighbor batch, dots in slots
// 0..15 / norms in 16..31), cutting SHFL traffic 320 -> 66 per warp since
// the L1/LSU pipe (82.8%) was shuffle-dominated.

#define FULLM 0xffffffffu
#define K_NEIGH 32

__global__ __launch_bounds__(256)
void intra_agg_kernel(const float* __restrict__ features,
                      const int*   __restrict__ nodes,
                      const int*   __restrict__ neighs,
                      const int*   __restrict__ nsp,   // may be null
                      float*       __restrict__ out,
                      int B)
{
    const int warp = (blockIdx.x * blockDim.x + threadIdx.x) >> 5;
    const int lane = threadIdx.x & 31;
    if (warp >= B) return;
    const int b = warp;

    int ns = (nsp != nullptr) ? __ldg(nsp) : 10;
    ns = min(max(ns, 1), K_NEIGH);

    const float4* __restrict__ f4 = reinterpret_cast<const float4*>(features);
    const int*    __restrict__ nrow = neighs + (long long)b * K_NEIGH;

    const int node = __ldg(&nodes[b]);
    const float4 c4 = __ldg(&f4[(long long)node * 32 + lane]);

    // ---------------- Phase 1: ranking scores, one per lane ----------------
    // Two batches of 16 neighbors. Per batch, fill 32 reduction slots:
    //   batch 0: slot j   = partial dot(n_j),  slot j+16 = partial |n_j|^2
    //   batch 1: slot j+16= partial dot(n_{16+j}), slot j = partial |n_{16+j}|^2
    // Transpose-reduce: after 5 halving stages, lane l holds the full sum of
    // original slot l. One shfl_xor(16) then pairs each lane's dot with its norm.
    float score = 0.0f;
    #pragma unroll
    for (int half = 0; half < 2; ++half) {
        const int base = half << 4;
        int r[16];
        #pragma unroll
        for (int j = 0; j < 16; ++j) r[j] = __ldg(&nrow[base + j]);

        float pv[32];
        #pragma unroll
        for (int j0 = 0; j0 < 16; j0 += 8) {
            float4 v[8];
            #pragma unroll
            for (int j = 0; j < 8; ++j)
                v[j] = __ldg(&f4[(long long)r[j0 + j] * 32 + lane]);
            #pragma unroll
            for (int j = 0; j < 8; ++j) {
                const int js = j0 + j;
                const float pd = c4.x * v[j].x + c4.y * v[j].y
                               + c4.z * v[j].z + c4.w * v[j].w;
                const float pn = v[j].x * v[j].x + v[j].y * v[j].y
                               + v[j].z * v[j].z + v[j].w * v[j].w;
                pv[half ? js + 16 : js] = pd;
                pv[half ? js : js + 16] = pn;
            }
        }

        // 32-slot transpose-reduction: 16+8+4+2+1 = 31 shuffles.
        #pragma unroll
        for (int o = 16; o >= 1; o >>= 1) {
            #pragma unroll
            for (int j = 0; j < o; ++j) {
                const float send = (lane & o) ? pv[j] : pv[j + o];
                const float recv = __shfl_xor_sync(FULLM, send, o);
                pv[j] = ((lane & o) ? pv[j + o] : pv[j]) + recv;
            }
        }
        const float mine  = pv[0];                       // lane l = sum(slot l)
        const float other = __shfl_xor_sync(FULLM, mine, 16);
        const float s = mine * rsqrtf(other);
        const bool valid = half ? (lane >= 16) : (lane < 16);
        if (valid) score = s;   // lane k now holds score of neighbor k
    }

    // ---------------- Phase 2: top-ns selection (set only) -----------------
    // Monotonic float->uint key; excluded lanes use 0 (below any finite key).
    unsigned u = __float_as_uint(score);
    u = (u & 0x80000000u) ? ~u : (u | 0x80000000u);

    unsigned sel = 0u;
    for (int i = 0; i < ns; ++i) {
        unsigned v = ((sel >> lane) & 1u) ? 0u : u;
        unsigned m = __reduce_max_sync(FULLM, v);
        unsigned bal = __ballot_sync(FULLM, v == m);
        sel |= 1u << (__ffs(bal) - 1);                // lowest index on ties
    }

    // ---------------- Phase 3: mean of selected rows + relu ----------------
    float ax = 0.f, ay = 0.f, az = 0.f, aw = 0.f;
    unsigned rem = sel;
    #pragma unroll 5
    for (int i = 0; i < ns; ++i) {
        const int k = __ffs(rem) - 1;
        rem &= rem - 1;
        const int rI = __ldg(&nrow[k]);               // uniform, L1-hot
        const float4 v = __ldg(&f4[(long long)rI * 32 + lane]);
        ax += v.x; ay += v.y; az += v.z; aw += v.w;
    }
    const float inv = 1.0f / (float)ns;
    float4 o;
    o.x = fmaxf(ax * inv, 0.0f);
    o.y = fmaxf(ay * inv, 0.0f);
    o.z = fmaxf(az * inv, 0.0f);
    o.w = fmaxf(aw * inv, 0.0f);
    reinterpret_cast<float4*>(out)[(long long)b * 32 + lane] = o;
}

extern "C" void kernel_launch(void* const* d_in, const int* in_sizes, int n_in,
                              void* d_out, int out_size)
{
    const float* features = (const float*)d_in[0];
    const int*   nodes    = (const int*)d_in[1];
    const int*   neighs   = (const int*)d_in[2];
    const int*   nsp      = (n_in > 3) ? (const int*)d_in[3] : nullptr;

    const int B = in_sizes[1];                 // nodes element count = batch
    const int threads = 256;                   // 8 warps = 8 rows per block
    const int rows_per_block = threads / 32;
    const int grid = (B + rows_per_block - 1) / rows_per_block;

    intra_agg_kernel<<<grid, threads>>>(features, nodes, neighs, nsp,
                                        (float*)d_out, B);
}